// round 1
// baseline (speedup 1.0000x reference)
#include <cuda_runtime.h>
#include <cstdint>

// Embedding gather on GB300:
//   x : [B*S] int32 token ids        (d_in[0], 16384 elems)
//   W : [DIMS=1024, TOKENS=50257] f32 row-major (d_in[1])
//   out[s, d] = W[d, x[s]]           (d_out, [16384, 1024] f32)
//
// W columns are strided (stride 50257 floats), so reads are inherently
// scattered 4B-in-32B-sector accesses; we maximize MLP (4 independent LDGs
// per thread) and make all writes coalesced 128-bit stores.

#define TOKENS 50257
#define DIMS   1024

__global__ __launch_bounds__(256, 8)
void embedding_gather_kernel(const int* __restrict__ x,
                             const float* __restrict__ W,
                             float4* __restrict__ out)
{
    const int s   = blockIdx.x;            // token position 0..16383
    const int tok = __ldg(&x[s]);          // broadcast via constant-like LDG

    const int d0 = threadIdx.x * 4;        // 4 consecutive dims per thread
    const float* col = W + tok;            // column base

    // 4 independent strided loads (each hits a distinct 32B sector).
    float4 v;
    v.x = __ldg(col + (size_t)(d0 + 0) * TOKENS);
    v.y = __ldg(col + (size_t)(d0 + 1) * TOKENS);
    v.z = __ldg(col + (size_t)(d0 + 2) * TOKENS);
    v.w = __ldg(col + (size_t)(d0 + 3) * TOKENS);

    // Coalesced 128-bit store: warp writes 512 contiguous bytes.
    out[(size_t)s * (DIMS / 4) + threadIdx.x] = v;
}

extern "C" void kernel_launch(void* const* d_in, const int* in_sizes, int n_in,
                              void* d_out, int out_size)
{
    const int*   x = (const int*)  d_in[0];   // [16384] int32
    const float* W = (const float*)d_in[1];   // [1024, 50257] f32
    float4*      o = (float4*)     d_out;     // [16384, 1024] f32

    const int n_tokens = in_sizes[0];         // 16384
    embedding_gather_kernel<<<n_tokens, 256>>>(x, W, o);
}

// round 2
// speedup vs baseline: 2.4091x; 2.4091x over previous
#include <cuda_runtime.h>
#include <cstdint>

// Embedding gather on GB300, L2-residency-aware:
//   x : [16384] int32 token ids       (d_in[0])
//   W : [DIMS=1024, TOKENS=50257] f32 (d_in[1], row-major; embeddings are columns)
//   out[s, d] = W[d, x[s]]
//
// Strategy: process dims in 4 chunks of 256. Per chunk, the distinct W
// sectors touched by all 16384 tokens (~5.8K distinct token sector-groups
// x 256 dims x 32B) is ~48 MB, which fits in the 126 MB L2. Grid launch
// order (x fastest) runs all tokens of chunk 0 before chunk 1, so every
// DRAM sector is fetched once per chunk and token-level sharing is served
// from L2. Output stores use st.global.wt so streaming writes don't evict
// the resident W working set.

#define TOKENS 50257
#define DIMS   1024
#define CHUNKS 4
#define DIMS_PER_CHUNK (DIMS / CHUNKS)        // 256
#define THREADS (DIMS_PER_CHUNK / 4)          // 64 threads, 4 dims each

__global__ __launch_bounds__(THREADS, 24)
void embedding_gather_chunked(const int* __restrict__ x,
                              const float* __restrict__ W,
                              float4* __restrict__ out)
{
    const int s     = blockIdx.x;                 // token position
    const int chunk = blockIdx.y;                 // dim chunk
    const int tok   = __ldg(&x[s]);

    const int d0 = chunk * DIMS_PER_CHUNK + threadIdx.x * 4;
    const float* col = W + tok;

    // 4 independent strided loads; sectors shared across tokens hit L2.
    float4 v;
    v.x = __ldg(col + (size_t)(d0 + 0) * TOKENS);
    v.y = __ldg(col + (size_t)(d0 + 1) * TOKENS);
    v.z = __ldg(col + (size_t)(d0 + 2) * TOKENS);
    v.w = __ldg(col + (size_t)(d0 + 3) * TOKENS);

    // Streaming write-through store: don't pollute L2 with output traffic.
    __stwt(&out[(size_t)s * (DIMS / 4) + chunk * (DIMS_PER_CHUNK / 4) + threadIdx.x], v);
}

extern "C" void kernel_launch(void* const* d_in, const int* in_sizes, int n_in,
                              void* d_out, int out_size)
{
    const int*   x = (const int*)  d_in[0];   // [16384] int32
    const float* W = (const float*)d_in[1];   // [1024, 50257] f32
    float4*      o = (float4*)     d_out;     // [16384, 1024] f32

    const int n_tokens = in_sizes[0];         // 16384
    dim3 grid(n_tokens, CHUNKS);
    embedding_gather_chunked<<<grid, THREADS>>>(x, W, o);
}